// round 9
// baseline (speedup 1.0000x reference)
#include <cuda_runtime.h>
#include <cstdint>

#define BS 32
#define NN 1024
#define FO 128
#define NWORDS 32

#define RW 8                   // rows per warp
#define WARPS 8
#define ROWS_PER_BLOCK 64      // RW * WARPS
#define PACK_BLOCKS 512

// Scratch (__device__ globals; no allocations allowed)
__device__ uint32_t g_adjw[NN * NWORDS];   // 128 KB packed adjacency
__device__ float4   g_pre[BS * NN];        // {s2, s1, e2, e2*x}  512 KB
__device__ float    g_meanx[BS];

// ---------------------------------------------------------------------------
// Setup: (a) pack adj via 2x LDG.128/thread + shfl byte-pack,
//        (b) one block per batch: c1,c2, mean(x), g_pre fill.
// ---------------------------------------------------------------------------
__global__ void __launch_bounds__(256) k_setup(const int* __restrict__ adj,
                                               const float* __restrict__ x,
                                               const float* __restrict__ W,
                                               const float* __restrict__ a) {
    int bid = blockIdx.x;
    int tid = threadIdx.x;

    if (bid < PACK_BLOCKS) {
        int t = bid * 256 + tid;
        const int4* a4 = reinterpret_cast<const int4*>(adj);
        int4 v0 = a4[2 * t];
        int4 v1 = a4[2 * t + 1];
        uint32_t m = 0;
        m |= (v0.x > 0) ? 1u   : 0u;
        m |= (v0.y > 0) ? 2u   : 0u;
        m |= (v0.z > 0) ? 4u   : 0u;
        m |= (v0.w > 0) ? 8u   : 0u;
        m |= (v1.x > 0) ? 16u  : 0u;
        m |= (v1.y > 0) ? 32u  : 0u;
        m |= (v1.z > 0) ? 64u  : 0u;
        m |= (v1.w > 0) ? 128u : 0u;
        int lane = tid & 31;
        uint32_t val = m << ((lane & 3) * 8);
        val |= __shfl_xor_sync(0xffffffffu, val, 1);
        val |= __shfl_xor_sync(0xffffffffu, val, 2);
        uint32_t w = __shfl_sync(0xffffffffu, val, (lane & 7) * 4);
        int wbase = (t >> 5) * 8;
        if (lane < 8) g_adjw[wbase + lane] = w;
        return;
    }

    int b = bid - PACK_BLOCKS;
    __shared__ float red[256];
    __shared__ float s_c1, s_c2;

    float p = (tid < FO) ? W[tid] * a[tid] : 0.f;
    red[tid] = p; __syncthreads();
    for (int st = 128; st > 0; st >>= 1) {
        if (tid < st) red[tid] += red[tid + st];
        __syncthreads();
    }
    if (tid == 0) s_c1 = red[0];
    __syncthreads();

    p = (tid < FO) ? W[tid] * a[FO + tid] : 0.f;
    red[tid] = p; __syncthreads();
    for (int st = 128; st > 0; st >>= 1) {
        if (tid < st) red[tid] += red[tid + st];
        __syncthreads();
    }
    if (tid == 0) s_c2 = red[0];
    __syncthreads();

    float s = 0.f;
    for (int n = tid; n < NN; n += 256) s += x[(size_t)b * NN + n];
    red[tid] = s; __syncthreads();
    for (int st = 128; st > 0; st >>= 1) {
        if (tid < st) red[tid] += red[tid + st];
        __syncthreads();
    }
    if (tid == 0) g_meanx[b] = red[0] * (1.0f / NN);

    float c1 = s_c1, c2 = s_c2;
    for (int n = tid; n < NN; n += 256) {
        float xv = x[(size_t)b * NN + n];
        float s2 = c2 * xv;
        float s1 = c1 * xv;
        float e2 = __expf(s2);
        g_pre[(size_t)b * NN + n] = make_float4(s2, s1, e2, e2 * xv);
    }
}

// ---------------------------------------------------------------------------
// Main: grid (16, 32), 256 threads, 1 batch/block, 64 rows/block.
// Warp = 8 rows. Per word: 2x LDS.128 adj + 1x LDS.128 pre serve 8 rows x 32 j
// -> 3 instrs per kept-test pair. Keep-predicate identical: bit && s2_j > -s1_i.
// ---------------------------------------------------------------------------
__device__ __forceinline__ float elu_fast(float v) {
    return v > 0.f ? v : (__expf(v) - 1.0f);
}

__global__ void __launch_bounds__(256, 4) k_main(const float* __restrict__ W,
                                                 float* __restrict__ out) {
    __shared__ float4   s_pre[NN];                       // 16 KB
    __shared__ uint32_t s_adjT[NWORDS][ROWS_PER_BLOCK];  // 8 KB, [word][row]
    __shared__ float    s_W[FO];                         // 512 B

    int tid  = threadIdx.x;
    int lane = tid & 31;
    int warp = tid >> 5;
    int row0 = blockIdx.x * ROWS_PER_BLOCK;
    int b    = blockIdx.y;

    // cooperative loads
    {
        const float4* src = &g_pre[(size_t)b * NN];
        for (int t = tid; t < NN; t += 256) s_pre[t] = src[t];
    }
    for (int t = tid; t < ROWS_PER_BLOCK * NWORDS; t += 256) {
        int r = t >> 5, kk = t & 31;
        s_adjT[kk][r] = g_adjw[(row0 + r) * NWORDS + kk];
    }
    if (tid < FO) s_W[tid] = W[tid];
    __syncthreads();

    const int ir = warp * RW;
    const uint32_t lanebit = 1u << lane;

    float thr[RW], den[RW], num[RW];
#pragma unroll
    for (int r = 0; r < RW; r++) {
        thr[r] = -s_pre[row0 + ir + r].y;   // -s1_i
        den[r] = 0.f;
        num[r] = 0.f;
    }

#pragma unroll 8
    for (int kk = 0; kk < NWORDS; kk++) {
        uint4 wa = *reinterpret_cast<const uint4*>(&s_adjT[kk][ir]);      // rows 0-3
        uint4 wb = *reinterpret_cast<const uint4*>(&s_adjT[kk][ir + 4]);  // rows 4-7
        float4 q = s_pre[kk * 32 + lane];   // {s2, s1, e2, e2x}
        bool p0 = (wa.x & lanebit) != 0;
        bool p1 = (wa.y & lanebit) != 0;
        bool p2 = (wa.z & lanebit) != 0;
        bool p3 = (wa.w & lanebit) != 0;
        bool p4 = (wb.x & lanebit) != 0;
        bool p5 = (wb.y & lanebit) != 0;
        bool p6 = (wb.z & lanebit) != 0;
        bool p7 = (wb.w & lanebit) != 0;
        if (p0 && (q.x > thr[0])) { den[0] += q.z; num[0] += q.w; }
        if (p1 && (q.x > thr[1])) { den[1] += q.z; num[1] += q.w; }
        if (p2 && (q.x > thr[2])) { den[2] += q.z; num[2] += q.w; }
        if (p3 && (q.x > thr[3])) { den[3] += q.z; num[3] += q.w; }
        if (p4 && (q.x > thr[4])) { den[4] += q.z; num[4] += q.w; }
        if (p5 && (q.x > thr[5])) { den[5] += q.z; num[5] += q.w; }
        if (p6 && (q.x > thr[6])) { den[6] += q.z; num[6] += q.w; }
        if (p7 && (q.x > thr[7])) { den[7] += q.z; num[7] += q.w; }
    }

    const float meanx = g_meanx[b];
    const float4 wv = reinterpret_cast<const float4*>(s_W)[lane];

#pragma unroll
    for (int r = 0; r < RW; r++) {
        float d = den[r], nm = num[r];
#pragma unroll
        for (int o = 16; o > 0; o >>= 1) {
            d  += __shfl_xor_sync(0xffffffffu, d,  o);
            nm += __shfl_xor_sync(0xffffffffu, nm, o);
        }
        float y = (d > 0.f) ? __fdividef(nm, d) : meanx;
        int i = row0 + ir + r;
        float4 z;
        z.x = elu_fast(y * wv.x);
        z.y = elu_fast(y * wv.y);
        z.z = elu_fast(y * wv.z);
        z.w = elu_fast(y * wv.w);
        reinterpret_cast<float4*>(out)[((size_t)b * NN + i) * (FO / 4) + lane] = z;
    }
}

// ---------------------------------------------------------------------------
// Inputs per metadata order: input, adj, ext_input, side_input, W, a
// ---------------------------------------------------------------------------
extern "C" void kernel_launch(void* const* d_in, const int* in_sizes, int n_in,
                              void* d_out, int out_size) {
    const float* input = (const float*)d_in[0];
    const int*   adj   = (const int*)  d_in[1];
    const float* W     = (const float*)d_in[4];
    const float* a     = (const float*)d_in[5];
    float* out = (float*)d_out;

    k_setup<<<PACK_BLOCKS + BS, 256>>>(adj, input, W, a);
    k_main<<<dim3(NN / ROWS_PER_BLOCK, BS), 256>>>(W, out);
}

// round 10
// speedup vs baseline: 1.0681x; 1.0681x over previous
#include <cuda_runtime.h>
#include <cstdint>

#define BS 32
#define NN 1024
#define FO 128
#define NWORDS 32

#define RW 2                   // rows per warp
#define BW 4                   // batches per block
#define WARPS 8
#define ROWS_PER_BLOCK 16      // RW * WARPS
#define PACK_BLOCKS 512

// Scratch (__device__ globals; no allocations allowed)
__device__ uint32_t g_adjw[NN * NWORDS];   // 128 KB packed adjacency
__device__ float    g_c1, g_c2;
__device__ float    g_meanx[BS];

// ---------------------------------------------------------------------------
// Setup (unchanged from best round): pack adj via 2x LDG.128/thread +
// shfl byte-pack; per-batch mean(x); scalars c1, c2.
// ---------------------------------------------------------------------------
__global__ void __launch_bounds__(256) k_setup(const int* __restrict__ adj,
                                               const float* __restrict__ x,
                                               const float* __restrict__ W,
                                               const float* __restrict__ a) {
    int bid = blockIdx.x;
    int tid = threadIdx.x;

    if (bid < PACK_BLOCKS) {
        int t = bid * 256 + tid;
        const int4* a4 = reinterpret_cast<const int4*>(adj);
        int4 v0 = a4[2 * t];
        int4 v1 = a4[2 * t + 1];
        uint32_t m = 0;
        m |= (v0.x > 0) ? 1u   : 0u;
        m |= (v0.y > 0) ? 2u   : 0u;
        m |= (v0.z > 0) ? 4u   : 0u;
        m |= (v0.w > 0) ? 8u   : 0u;
        m |= (v1.x > 0) ? 16u  : 0u;
        m |= (v1.y > 0) ? 32u  : 0u;
        m |= (v1.z > 0) ? 64u  : 0u;
        m |= (v1.w > 0) ? 128u : 0u;
        int lane = tid & 31;
        uint32_t val = m << ((lane & 3) * 8);
        val |= __shfl_xor_sync(0xffffffffu, val, 1);
        val |= __shfl_xor_sync(0xffffffffu, val, 2);
        uint32_t w = __shfl_sync(0xffffffffu, val, (lane & 7) * 4);
        int wbase = (t >> 5) * 8;
        if (lane < 8) g_adjw[wbase + lane] = w;
        return;
    }

    __shared__ float red[256];

    if (bid < PACK_BLOCKS + BS) {
        int b = bid - PACK_BLOCKS;
        float s = 0.f;
        for (int n = tid; n < NN; n += 256) s += x[(size_t)b * NN + n];
        red[tid] = s; __syncthreads();
        for (int st = 128; st > 0; st >>= 1) {
            if (tid < st) red[tid] += red[tid + st];
            __syncthreads();
        }
        if (tid == 0) g_meanx[b] = red[0] * (1.0f / NN);
        return;
    }

    float p = (tid < FO) ? W[tid] * a[tid] : 0.f;
    red[tid] = p; __syncthreads();
    for (int st = 128; st > 0; st >>= 1) {
        if (tid < st) red[tid] += red[tid + st];
        __syncthreads();
    }
    if (tid == 0) g_c1 = red[0];
    __syncthreads();

    p = (tid < FO) ? W[tid] * a[FO + tid] : 0.f;
    red[tid] = p; __syncthreads();
    for (int st = 128; st > 0; st >>= 1) {
        if (tid < st) red[tid] += red[tid + st];
        __syncthreads();
    }
    if (tid == 0) g_c2 = red[0];
}

// ---------------------------------------------------------------------------
// Main: grid (64, 8), 256 threads, 4 batches/block, 16 rows/block.
// Warp = 2 rows x 4 batches. Bit-pred amortized over 4 batches inside one
// asm group; (den,num) accumulated with ONE predicated add.rn.f32x2.
// Keep-predicate identical: adj bit && (s2_j > -c1*x_i).
// ---------------------------------------------------------------------------
__device__ __forceinline__ float elu_fast(float v) {
    return v > 0.f ? v : (__expf(v) - 1.0f);
}

// One row vs 4 batches: bp = (wr != 0) once, then per batch
// kp = (s2_b > thr_b) && bp ; @kp acc_b += (e2, e2x) packed.
#define ROW_ACC(ACC0, ACC1, ACC2, ACC3, WR, S0, T0, Q0, S1, T1, Q1, S2_, T2, Q2, S3, T3, Q3) \
    asm ("{\n\t"                                            \
         ".reg .pred bp, kp;\n\t"                           \
         "setp.ne.u32 bp, %4, 0;\n\t"                       \
         "setp.gt.and.f32 kp, %5, %6, bp;\n\t"              \
         "@kp add.rn.f32x2 %0, %0, %7;\n\t"                 \
         "setp.gt.and.f32 kp, %8, %9, bp;\n\t"              \
         "@kp add.rn.f32x2 %1, %1, %10;\n\t"                \
         "setp.gt.and.f32 kp, %11, %12, bp;\n\t"            \
         "@kp add.rn.f32x2 %2, %2, %13;\n\t"                \
         "setp.gt.and.f32 kp, %14, %15, bp;\n\t"            \
         "@kp add.rn.f32x2 %3, %3, %16;\n\t"                \
         "}"                                                \
         : "+l"(ACC0), "+l"(ACC1), "+l"(ACC2), "+l"(ACC3)   \
         : "r"(WR),                                         \
           "f"(S0), "f"(T0), "l"(Q0),                       \
           "f"(S1), "f"(T1), "l"(Q1),                       \
           "f"(S2_), "f"(T2), "l"(Q2),                      \
           "f"(S3), "f"(T3), "l"(Q3))

__global__ void __launch_bounds__(256, 4) k_main(const float* __restrict__ x,
                                                 const float* __restrict__ W,
                                                 float* __restrict__ out) {
    __shared__ float2   s_q2[BW][NN];                    // 32 KB {e2, e2*x}
    __shared__ float    s_s2[BW][NN];                    // 16 KB s2
    __shared__ uint32_t s_adjT[NWORDS][ROWS_PER_BLOCK];  // 2 KB [word][row]
    __shared__ float    s_W[FO];                         // 512 B

    int tid  = threadIdx.x;
    int lane = tid & 31;
    int warp = tid >> 5;
    int row0 = blockIdx.x * ROWS_PER_BLOCK;
    int b0   = blockIdx.y * BW;

    const float c1 = g_c1, c2 = g_c2;

    // Prologue: build per-batch {s2, e2, e2x} tables from x (16 exps/thread).
    {
        const float4* x4 = reinterpret_cast<const float4*>(x + (size_t)b0 * NN);
        for (int t = tid; t < BW * NN / 4; t += 256) {
            int b = t >> 8, j4 = t & 255;
            float4 v = x4[t];
            float s2a = c2 * v.x, s2b = c2 * v.y, s2c = c2 * v.z, s2d = c2 * v.w;
            float ea = __expf(s2a), eb = __expf(s2b), ec = __expf(s2c), ed = __expf(s2d);
            int j = j4 * 4;
            s_s2[b][j]     = s2a; s_q2[b][j]     = make_float2(ea, ea * v.x);
            s_s2[b][j + 1] = s2b; s_q2[b][j + 1] = make_float2(eb, eb * v.y);
            s_s2[b][j + 2] = s2c; s_q2[b][j + 2] = make_float2(ec, ec * v.z);
            s_s2[b][j + 3] = s2d; s_q2[b][j + 3] = make_float2(ed, ed * v.w);
        }
    }
    for (int t = tid; t < ROWS_PER_BLOCK * NWORDS; t += 256) {
        int r = t >> 5, kk = t & 31;
        s_adjT[kk][r] = g_adjw[(row0 + r) * NWORDS + kk];
    }
    if (tid < FO) s_W[tid] = W[tid];
    __syncthreads();

    const int ir = warp * RW;
    const uint32_t lanebit = 1u << lane;

    // thresholds: thr = -c1 * x_i (per row, per batch)
    float thr[RW][BW];
#pragma unroll
    for (int r = 0; r < RW; r++)
#pragma unroll
        for (int b = 0; b < BW; b++)
            thr[r][b] = -c1 * x[(size_t)(b0 + b) * NN + row0 + ir + r];

    unsigned long long acc0[BW], acc1[BW];   // packed (den, num) per batch, rows 0/1
#pragma unroll
    for (int b = 0; b < BW; b++) { acc0[b] = 0ull; acc1[b] = 0ull; }

#pragma unroll 8
    for (int kk = 0; kk < NWORDS; kk++) {
        uint2 w2 = *reinterpret_cast<const uint2*>(&s_adjT[kk][ir]);  // LDS.64
        uint32_t wr0 = w2.x & lanebit;
        uint32_t wr1 = w2.y & lanebit;

        float s2v[BW];
        unsigned long long q[BW];
#pragma unroll
        for (int b = 0; b < BW; b++) {
            int j = kk * 32 + lane;
            s2v[b] = s_s2[b][j];
            q[b]   = *reinterpret_cast<const unsigned long long*>(&s_q2[b][j]); // LDS.64
        }

        ROW_ACC(acc0[0], acc0[1], acc0[2], acc0[3], wr0,
                s2v[0], thr[0][0], q[0],
                s2v[1], thr[0][1], q[1],
                s2v[2], thr[0][2], q[2],
                s2v[3], thr[0][3], q[3]);
        ROW_ACC(acc1[0], acc1[1], acc1[2], acc1[3], wr1,
                s2v[0], thr[1][0], q[0],
                s2v[1], thr[1][1], q[1],
                s2v[2], thr[1][2], q[2],
                s2v[3], thr[1][3], q[3]);
    }

    const float4 wv = reinterpret_cast<const float4*>(s_W)[lane];

#pragma unroll
    for (int r = 0; r < RW; r++) {
        int i = row0 + ir + r;
#pragma unroll
        for (int b = 0; b < BW; b++) {
            unsigned long long a = (r == 0) ? acc0[b] : acc1[b];
            float d  = __uint_as_float((uint32_t)(a & 0xffffffffull));
            float nm = __uint_as_float((uint32_t)(a >> 32));
#pragma unroll
            for (int o = 16; o > 0; o >>= 1) {
                d  += __shfl_xor_sync(0xffffffffu, d,  o);
                nm += __shfl_xor_sync(0xffffffffu, nm, o);
            }
            float y = (d > 0.f) ? __fdividef(nm, d) : g_meanx[b0 + b];
            float4 z;
            z.x = elu_fast(y * wv.x);
            z.y = elu_fast(y * wv.y);
            z.z = elu_fast(y * wv.z);
            z.w = elu_fast(y * wv.w);
            reinterpret_cast<float4*>(out)[((size_t)(b0 + b) * NN + i) * (FO / 4) + lane] = z;
        }
    }
}

// ---------------------------------------------------------------------------
// Inputs per metadata order: input, adj, ext_input, side_input, W, a
// ---------------------------------------------------------------------------
extern "C" void kernel_launch(void* const* d_in, const int* in_sizes, int n_in,
                              void* d_out, int out_size) {
    const float* input = (const float*)d_in[0];
    const int*   adj   = (const int*)  d_in[1];
    const float* W     = (const float*)d_in[4];
    const float* a     = (const float*)d_in[5];
    float* out = (float*)d_out;

    k_setup<<<PACK_BLOCKS + BS + 1, 256>>>(adj, input, W, a);
    k_main<<<dim3(NN / ROWS_PER_BLOCK, BS / BW), 256>>>(input, W, out);
}

// round 11
// speedup vs baseline: 1.2838x; 1.2020x over previous
#include <cuda_runtime.h>
#include <cstdint>

#define BS 32
#define NN 1024
#define FO 128
#define NWORDS 32

#define RW 2                   // rows per warp
#define BW 2                   // batches per block
#define WARPS 4                // 128 threads
#define ROWS_PER_BLOCK 8       // RW * WARPS
#define PACK_BLOCKS 512

// Scratch (__device__ globals; no allocations allowed)
__device__ uint32_t g_adjw[NN * NWORDS];   // 128 KB packed adjacency
__device__ float    g_c1, g_c2;
__device__ float    g_meanx[BS];

// ---------------------------------------------------------------------------
// Setup: pack adj via 2x LDG.128/thread + shfl byte-pack; per-batch mean(x);
// scalars c1, c2. (Unchanged from best-known round.)
// ---------------------------------------------------------------------------
__global__ void __launch_bounds__(256) k_setup(const int* __restrict__ adj,
                                               const float* __restrict__ x,
                                               const float* __restrict__ W,
                                               const float* __restrict__ a) {
    int bid = blockIdx.x;
    int tid = threadIdx.x;

    if (bid < PACK_BLOCKS) {
        int t = bid * 256 + tid;
        const int4* a4 = reinterpret_cast<const int4*>(adj);
        int4 v0 = a4[2 * t];
        int4 v1 = a4[2 * t + 1];
        uint32_t m = 0;
        m |= (v0.x > 0) ? 1u   : 0u;
        m |= (v0.y > 0) ? 2u   : 0u;
        m |= (v0.z > 0) ? 4u   : 0u;
        m |= (v0.w > 0) ? 8u   : 0u;
        m |= (v1.x > 0) ? 16u  : 0u;
        m |= (v1.y > 0) ? 32u  : 0u;
        m |= (v1.z > 0) ? 64u  : 0u;
        m |= (v1.w > 0) ? 128u : 0u;
        int lane = tid & 31;
        uint32_t val = m << ((lane & 3) * 8);
        val |= __shfl_xor_sync(0xffffffffu, val, 1);
        val |= __shfl_xor_sync(0xffffffffu, val, 2);
        uint32_t w = __shfl_sync(0xffffffffu, val, (lane & 7) * 4);
        int wbase = (t >> 5) * 8;
        if (lane < 8) g_adjw[wbase + lane] = w;
        return;
    }

    __shared__ float red[256];

    if (bid < PACK_BLOCKS + BS) {
        int b = bid - PACK_BLOCKS;
        float s = 0.f;
        for (int n = tid; n < NN; n += 256) s += x[(size_t)b * NN + n];
        red[tid] = s; __syncthreads();
        for (int st = 128; st > 0; st >>= 1) {
            if (tid < st) red[tid] += red[tid + st];
            __syncthreads();
        }
        if (tid == 0) g_meanx[b] = red[0] * (1.0f / NN);
        return;
    }

    float p = (tid < FO) ? W[tid] * a[tid] : 0.f;
    red[tid] = p; __syncthreads();
    for (int st = 128; st > 0; st >>= 1) {
        if (tid < st) red[tid] += red[tid + st];
        __syncthreads();
    }
    if (tid == 0) g_c1 = red[0];
    __syncthreads();

    p = (tid < FO) ? W[tid] * a[FO + tid] : 0.f;
    red[tid] = p; __syncthreads();
    for (int st = 128; st > 0; st >>= 1) {
        if (tid < st) red[tid] += red[tid + st];
        __syncthreads();
    }
    if (tid == 0) g_c2 = red[0];
}

// ---------------------------------------------------------------------------
// Main: 2048 small blocks (128 thr) for occupancy. Warp = 2 rows x 2 batches.
// Lean R7-style loop: recompute s2/e2 from smem x; adj via transposed LDS.64.
// Keep-predicate identical: adj bit && (c2*x_j > -c1*x_i).
// ---------------------------------------------------------------------------
__device__ __forceinline__ float elu_fast(float v) {
    return v > 0.f ? v : (__expf(v) - 1.0f);
}

__global__ void __launch_bounds__(128, 12) k_main(const float* __restrict__ x,
                                                  const float* __restrict__ W,
                                                  float* __restrict__ out) {
    __shared__ float    s_x[BW][NN];                     // 8 KB
    __shared__ uint32_t s_adjT[NWORDS][ROWS_PER_BLOCK];  // 1 KB [word][row]
    __shared__ float    s_W[FO];                         // 512 B

    int tid  = threadIdx.x;
    int lane = tid & 31;
    int warp = tid >> 5;
    int row0 = blockIdx.x * ROWS_PER_BLOCK;
    int b0   = blockIdx.y * BW;

    // cooperative loads
    {
        const float4* src = reinterpret_cast<const float4*>(x + (size_t)b0 * NN);
        float4* dst = reinterpret_cast<float4*>(&s_x[0][0]);
        for (int t = tid; t < BW * NN / 4; t += 128) dst[t] = src[t];
    }
    {
        int t = tid;                      // 256 words, 128 threads: 2 each
        int r = t >> 5, kk = t & 31;
        s_adjT[kk][r] = g_adjw[(row0 + r) * NWORDS + kk];
        r += 4;
        s_adjT[kk][r] = g_adjw[(row0 + r) * NWORDS + kk];
    }
    s_W[tid] = W[tid];
    __syncthreads();

    const float c1 = g_c1, c2 = g_c2;
    const int ir = warp * RW;
    const uint32_t lanebit = 1u << lane;

    float thr[RW][BW], den[RW][BW], num[RW][BW];
#pragma unroll
    for (int r = 0; r < RW; r++)
#pragma unroll
        for (int b = 0; b < BW; b++) {
            thr[r][b] = -c1 * s_x[b][row0 + ir + r];
            den[r][b] = 0.f;
            num[r][b] = 0.f;
        }

#pragma unroll 8
    for (int kk = 0; kk < NWORDS; kk++) {
        uint2 w2 = *reinterpret_cast<const uint2*>(&s_adjT[kk][ir]);  // LDS.64
        bool p0 = (w2.x & lanebit) != 0;
        bool p1 = (w2.y & lanebit) != 0;
#pragma unroll
        for (int b = 0; b < BW; b++) {
            float xv = s_x[b][kk * 32 + lane];
            float s2 = c2 * xv;
            float e2 = __expf(s2);
            if (p0 && (s2 > thr[0][b])) { den[0][b] += e2; num[0][b] = fmaf(e2, xv, num[0][b]); }
            if (p1 && (s2 > thr[1][b])) { den[1][b] += e2; num[1][b] = fmaf(e2, xv, num[1][b]); }
        }
    }

    const float4 wv = reinterpret_cast<const float4*>(s_W)[lane];

#pragma unroll
    for (int r = 0; r < RW; r++) {
        int i = row0 + ir + r;
#pragma unroll
        for (int b = 0; b < BW; b++) {
            float d = den[r][b], nm = num[r][b];
#pragma unroll
            for (int o = 16; o > 0; o >>= 1) {
                d  += __shfl_xor_sync(0xffffffffu, d,  o);
                nm += __shfl_xor_sync(0xffffffffu, nm, o);
            }
            float y = (d > 0.f) ? __fdividef(nm, d) : g_meanx[b0 + b];
            float4 z;
            z.x = elu_fast(y * wv.x);
            z.y = elu_fast(y * wv.y);
            z.z = elu_fast(y * wv.z);
            z.w = elu_fast(y * wv.w);
            reinterpret_cast<float4*>(out)[((size_t)(b0 + b) * NN + i) * (FO / 4) + lane] = z;
        }
    }
}

// ---------------------------------------------------------------------------
// Inputs per metadata order: input, adj, ext_input, side_input, W, a
// ---------------------------------------------------------------------------
extern "C" void kernel_launch(void* const* d_in, const int* in_sizes, int n_in,
                              void* d_out, int out_size) {
    const float* input = (const float*)d_in[0];
    const int*   adj   = (const int*)  d_in[1];
    const float* W     = (const float*)d_in[4];
    const float* a     = (const float*)d_in[5];
    float* out = (float*)d_out;

    k_setup<<<PACK_BLOCKS + BS + 1, 256>>>(adj, input, W, a);
    k_main<<<dim3(NN / ROWS_PER_BLOCK, BS / BW), 128>>>(input, W, out);
}